// round 10
// baseline (speedup 1.0000x reference)
#include <cuda_runtime.h>
#include <cstdint>

// MaxFeatBlockDescriptorLayer, fused single launch (R7 skeleton, proven):
//   128 blocks; block (b,chunk) reduces 256 positions x 8 classes of prob in
//   registers (thread = position, warp shuffle per class, ballot for
//   first-index ties). NEW in R9: no smem combine -- lanes 0..7 of each warp
//   publish per-warp slots directly, layout [b][chunk][w][c] so the 8 stores
//   form one 128B transaction. Producer path = load -> shuffles -> store.
//   Blocks with chunk<8 also gather (class k = chunk): ALL 8 warps poll
//   (warp w polls the 64 slots (chunk',w,k), 2 per lane, nanosleep backoff,
//   memory-clobbered .cg ops as in R7), reduce, combine via 8-entry smem
//   tile, reset own slots (sole reader -> replay-safe), then 256 threads
//   gather emb[b, argmax, :] * mask.
//
// argmax tie-break = first index: ballot lowest lane in-warp; packed
// (bits(v)<<32)|(N_POS-1-idx) max across warps/chunks (prob >= 0 so float
// bits are order-monotonic).

#define N_POS    16384
#define N_CLS    8
#define C_DIM    2048
#define TAU      0.3f
#define CHUNKS   64
#define POS_PC   (N_POS / CHUNKS)        // 256
#define NTHREADS 256
#define MAX_B    8

// slot idx = ((b*CHUNKS + chunk)*8 + w)*8 + c ; {pack lo, pack hi, sum, flag}
__device__ uint4 g_slot[MAX_B * CHUNKS * N_CLS * N_CLS];

__device__ __forceinline__ void slot_store(uint4* p, uint4 v) {
    asm volatile("st.global.cg.v4.u32 [%0], {%1,%2,%3,%4};"
                 :: "l"(p), "r"(v.x), "r"(v.y), "r"(v.z), "r"(v.w)
                 : "memory");
}
__device__ __forceinline__ uint4 slot_load(const uint4* p) {
    uint4 r;
    asm volatile("ld.global.cg.v4.u32 {%0,%1,%2,%3}, [%4];"
                 : "=r"(r.x), "=r"(r.y), "=r"(r.z), "=r"(r.w)
                 : "l"(p) : "memory");
    return r;
}

__global__ __launch_bounds__(NTHREADS)
void mfbd_fused(const float* __restrict__ emb,
                const float* __restrict__ prob,
                float* __restrict__ out)
{
    const int t    = threadIdx.x;
    const int w    = t >> 5;
    const int lane = t & 31;

    const int b     = blockIdx.x / CHUNKS;
    const int chunk = blockIdx.x % CHUNKS;

    __shared__ unsigned long long s_gpk[N_CLS];
    __shared__ float              s_gsm[N_CLS];
    __shared__ int   s_arg;
    __shared__ float s_mask;

    // ---------------- Producer: thread = one position, regs only ------------
    const float4* __restrict__ p4 =
        (const float4*)(prob + ((size_t)b * N_POS + (size_t)chunk * POS_PC) * N_CLS);
    const float4 a0 = __ldg(p4 + 2 * t);
    const float4 a1 = __ldg(p4 + 2 * t + 1);
    const float v[8] = { a0.x, a0.y, a0.z, a0.w, a1.x, a1.y, a1.z, a1.w };

    unsigned long long my_pk = 0ULL;
    float              my_sum = 0.0f;

    #pragma unroll
    for (int c = 0; c < N_CLS; ++c) {
        float m = v[c];
        float s = v[c];
        #pragma unroll
        for (int off = 16; off > 0; off >>= 1) {
            m = fmaxf(m, __shfl_xor_sync(0xffffffffu, m, off));
            s += __shfl_xor_sync(0xffffffffu, s, off);
        }
        const unsigned bal = __ballot_sync(0xffffffffu, v[c] == m);
        const int src  = __ffs(bal) - 1;                // lowest lane = first idx
        const int gidx = chunk * POS_PC + w * 32 + src;
        if (lane == c) {
            my_pk  = ((unsigned long long)__float_as_uint(m) << 32)
                   | (unsigned)(N_POS - 1 - gidx);
            my_sum = s;
        }
    }

    // Direct publish: lanes 0..7 -> 8 contiguous uint4 (one 128B transaction)
    if (lane < N_CLS) {
        uint4 sl;
        sl.x = (unsigned)(my_pk & 0xffffffffu);
        sl.y = (unsigned)(my_pk >> 32);
        sl.z = __float_as_uint(my_sum);
        sl.w = 1u;                                       // flag
        slot_store(&g_slot[(((size_t)(b * CHUNKS + chunk) * N_CLS + w) * N_CLS) + lane], sl);
    }

    // ---------------- Gather blocks: chunk < 8 -> class k = chunk -----------
    if (chunk >= N_CLS) return;
    const int k = chunk;

    // Warp w polls slots (chunk', w, k), chunk' = lane and lane+32.
    {
        uint4 r0, r1;
        uint4* const sl0 = &g_slot[(((size_t)(b * CHUNKS + lane)      * N_CLS + w) * N_CLS) + k];
        uint4* const sl1 = &g_slot[(((size_t)(b * CHUNKS + lane + 32) * N_CLS + w) * N_CLS) + k];
        for (;;) {
            r0 = slot_load(sl0);
            r1 = slot_load(sl1);
            if (__all_sync(0xffffffffu, (r0.w & r1.w) != 0u)) break;
            __nanosleep(32);
        }
        const unsigned long long p0 = ((unsigned long long)r0.y << 32) | r0.x;
        const unsigned long long p1 = ((unsigned long long)r1.y << 32) | r1.x;
        unsigned long long pk = p0 > p1 ? p0 : p1;
        float s = __uint_as_float(r0.z) + __uint_as_float(r1.z);
        #pragma unroll
        for (int off = 16; off > 0; off >>= 1) {
            const unsigned long long o = __shfl_xor_sync(0xffffffffu, pk, off);
            pk = pk > o ? pk : o;
            s += __shfl_xor_sync(0xffffffffu, s, off);
        }
        if (lane == 0) {
            s_gpk[w] = pk;
            s_gsm[w] = s;
        }
        // replay-safe reset: this warp is the sole reader of these slots
        const uint4 z = make_uint4(0u, 0u, 0u, 0u);
        slot_store(sl0, z);
        slot_store(sl1, z);
    }
    __syncthreads();

    if (w == 0 && lane < N_CLS) {
        unsigned long long pk = s_gpk[lane];
        float s = s_gsm[lane];
        #pragma unroll
        for (int off = 4; off > 0; off >>= 1) {
            const unsigned long long o = __shfl_xor_sync(0xffu, pk, off);
            pk = pk > o ? pk : o;
            s += __shfl_xor_sync(0xffu, s, off);
        }
        if (lane == 0) {
            s_arg  = N_POS - 1 - (int)(unsigned)(pk & 0xffffffffu);
            s_mask = (s * (1.0f / N_POS) > TAU) ? 1.0f : 0.0f;
        }
    }
    __syncthreads();

    // ---------------- Gather emb[b, arg, :] * mask ----------------
    const float4* __restrict__ src =
        (const float4*)(emb + ((size_t)b * N_POS + (size_t)s_arg) * C_DIM);
    float4* __restrict__ dst =
        (float4*)(out + ((size_t)b * N_CLS + (size_t)k) * C_DIM);

    const float m = s_mask;
    float4 v0 = __ldg(src + t);
    float4 v1 = __ldg(src + t + NTHREADS);
    v0.x *= m; v0.y *= m; v0.z *= m; v0.w *= m;
    v1.x *= m; v1.y *= m; v1.z *= m; v1.w *= m;
    dst[t]            = v0;
    dst[t + NTHREADS] = v1;
}

extern "C" void kernel_launch(void* const* d_in, const int* in_sizes, int n_in,
                              void* d_out, int out_size)
{
    const float* emb  = (const float*)d_in[0];
    const float* prob = (const float*)d_in[1];
    float* out = (float*)d_out;

    const int B = in_sizes[0] / (N_POS * C_DIM);   // = 2

    mfbd_fused<<<B * CHUNKS, NTHREADS>>>(emb, prob, out);   // 128 blocks, 1 wave
}